// round 2
// baseline (speedup 1.0000x reference)
#include <cuda_runtime.h>
#include <cuda_bf16.h>
#include <math.h>

// Problem shape (fixed by setup_inputs): B=8, N=M=4096, C=128, fp32.
#define NPTS 4096
#define CDIM 128
#define BMAX 8

#define BM 128
#define BN 128
#define BK 16
#define TM 8
#define TN 8
// 256 threads: 16x16 thread grid, each thread owns an 8x8 sub-tile.

// Scratch (allocation-free rule: __device__ globals)
__device__ float        g_sq1[BMAX * NPTS];
__device__ float        g_sq2[BMAX * NPTS];
__device__ unsigned int g_rowmin[BMAX * NPTS];
__device__ unsigned int g_colmin[BMAX * NPTS];

// ---------------------------------------------------------------------------
// Kernel 1: per-point squared norms + init min-scratch to +inf
// One thread per point (both sets). idx in [0, 2*B*NPTS)
// ---------------------------------------------------------------------------
__global__ void prep_kernel(const float* __restrict__ s1,
                            const float* __restrict__ s2, int B) {
    int idx = blockIdx.x * blockDim.x + threadIdx.x;
    int total = B * NPTS;
    const float* src;
    float* dst_sq;
    unsigned int* dst_min;
    int p;
    if (idx < total) {
        src = s1; dst_sq = g_sq1; dst_min = g_rowmin; p = idx;
    } else if (idx < 2 * total) {
        src = s2; dst_sq = g_sq2; dst_min = g_colmin; p = idx - total;
    } else {
        return;
    }
    const float4* v = (const float4*)(src + (size_t)p * CDIM);
    float s = 0.0f;
#pragma unroll
    for (int i = 0; i < CDIM / 4; i++) {
        float4 f = v[i];
        s += f.x * f.x + f.y * f.y + f.z * f.z + f.w * f.w;
    }
    dst_sq[p] = s;
    dst_min[p] = 0x7F800000u;  // +inf bit pattern
}

// ---------------------------------------------------------------------------
// Kernel 2: fused tile GEMM (inner products) + d2 + row/col min tracking.
// Grid: (M/BN, N/BM, B). Block: 256 threads.
// ---------------------------------------------------------------------------
__global__ __launch_bounds__(256, 2)
void tile_min_kernel(const float* __restrict__ s1,
                     const float* __restrict__ s2) {
    const int b  = blockIdx.z;
    const int nt = blockIdx.y;  // row tile (set1)
    const int mt = blockIdx.x;  // col tile (set2)

    const float* Ag = s1 + ((size_t)b * NPTS + nt * BM) * CDIM;
    const float* Bg = s2 + ((size_t)b * NPTS + mt * BN) * CDIM;

    __shared__ float As[BK][BM];
    __shared__ float Bs[BK][BN];
    __shared__ unsigned int rmin_s[BM];
    __shared__ unsigned int cmin_s[BN];

    const int tid = threadIdx.x;
    if (tid < BM) {
        rmin_s[tid] = 0x7F800000u;
        cmin_s[tid] = 0x7F800000u;
    }

    const int tx = tid & 15;   // 0..15  -> col group of 8
    const int ty = tid >> 4;   // 0..15  -> row group of 8

    float acc[TM][TN];
#pragma unroll
    for (int i = 0; i < TM; i++)
#pragma unroll
        for (int j = 0; j < TN; j++) acc[i][j] = 0.0f;

    // Loader mapping: each thread loads two float4 per tile per matrix.
    const int lr = tid >> 2;          // 0..63 (rows; two passes: +0, +64)
    const int lc = (tid & 3) * 4;     // k offset within BK: 0,4,8,12

    for (int k0 = 0; k0 < CDIM; k0 += BK) {
        __syncthreads();  // protect smem reuse from prior compute
#pragma unroll
        for (int p = 0; p < 2; p++) {
            const int r = lr + p * 64;
            float4 a = *(const float4*)(Ag + (size_t)r * CDIM + k0 + lc);
            As[lc + 0][r] = a.x; As[lc + 1][r] = a.y;
            As[lc + 2][r] = a.z; As[lc + 3][r] = a.w;
            float4 bb = *(const float4*)(Bg + (size_t)r * CDIM + k0 + lc);
            Bs[lc + 0][r] = bb.x; Bs[lc + 1][r] = bb.y;
            Bs[lc + 2][r] = bb.z; Bs[lc + 3][r] = bb.w;
        }
        __syncthreads();
#pragma unroll
        for (int k = 0; k < BK; k++) {
            float ar[TM], br[TN];
            float4 a0 = *(const float4*)&As[k][ty * TM];
            float4 a1 = *(const float4*)&As[k][ty * TM + 4];
            ar[0] = a0.x; ar[1] = a0.y; ar[2] = a0.z; ar[3] = a0.w;
            ar[4] = a1.x; ar[5] = a1.y; ar[6] = a1.z; ar[7] = a1.w;
            float4 b0 = *(const float4*)&Bs[k][tx * TN];
            float4 b1 = *(const float4*)&Bs[k][tx * TN + 4];
            br[0] = b0.x; br[1] = b0.y; br[2] = b0.z; br[3] = b0.w;
            br[4] = b1.x; br[5] = b1.y; br[6] = b1.z; br[7] = b1.w;
#pragma unroll
            for (int i = 0; i < TM; i++)
#pragma unroll
                for (int j = 0; j < TN; j++)
                    acc[i][j] += ar[i] * br[j];
        }
    }

    // Epilogue: d2 = sq1[n] + sq2[m] - 2*inner, clamp >= 0; track mins.
    const int rowg = b * NPTS + nt * BM + ty * TM;
    const int colg = b * NPTS + mt * BN + tx * TN;
    float rs[TM], cs[TN];
#pragma unroll
    for (int i = 0; i < TM; i++) rs[i] = g_sq1[rowg + i];
#pragma unroll
    for (int j = 0; j < TN; j++) cs[j] = g_sq2[colg + j];

    float rm[TM], cm[TN];
#pragma unroll
    for (int i = 0; i < TM; i++) rm[i] = INFINITY;
#pragma unroll
    for (int j = 0; j < TN; j++) cm[j] = INFINITY;

#pragma unroll
    for (int i = 0; i < TM; i++) {
#pragma unroll
        for (int j = 0; j < TN; j++) {
            float d2 = fmaxf(rs[i] + cs[j] - 2.0f * acc[i][j], 0.0f);
            rm[i] = fminf(rm[i], d2);
            cm[j] = fminf(cm[j], d2);
        }
    }

    __syncthreads();  // rmin_s/cmin_s init + loop smem done
#pragma unroll
    for (int i = 0; i < TM; i++)
        atomicMin(&rmin_s[ty * TM + i], __float_as_uint(rm[i]));
#pragma unroll
    for (int j = 0; j < TN; j++)
        atomicMin(&cmin_s[tx * TN + j], __float_as_uint(cm[j]));
    __syncthreads();

    if (tid < BM) {
        atomicMin(&g_rowmin[b * NPTS + nt * BM + tid], rmin_s[tid]);
        atomicMin(&g_colmin[b * NPTS + mt * BN + tid], cmin_s[tid]);
    }
}

// ---------------------------------------------------------------------------
// Kernel 3: finalize. One block per batch. N == M so both means share /NPTS.
// ---------------------------------------------------------------------------
__global__ void final_kernel(float* __restrict__ out) {
    const int b = blockIdx.x;
    const int tid = threadIdx.x;
    float s = 0.0f;
    for (int i = tid; i < NPTS; i += blockDim.x) {
        s += sqrtf(__uint_as_float(g_rowmin[b * NPTS + i]));
        s += sqrtf(__uint_as_float(g_colmin[b * NPTS + i]));
    }
    __shared__ float red[256];
    red[tid] = s;
    __syncthreads();
    for (int stride = 128; stride > 0; stride >>= 1) {
        if (tid < stride) red[tid] += red[tid + stride];
        __syncthreads();
    }
    if (tid == 0) out[b] = red[0] / (float)NPTS;
}

// ---------------------------------------------------------------------------
extern "C" void kernel_launch(void* const* d_in, const int* in_sizes, int n_in,
                              void* d_out, int out_size) {
    const float* s1 = (const float*)d_in[0];
    const float* s2 = (const float*)d_in[1];
    float* out = (float*)d_out;

    const int B = in_sizes[0] / (NPTS * CDIM);  // 8

    const int prep_threads = 2 * B * NPTS;
    prep_kernel<<<(prep_threads + 255) / 256, 256>>>(s1, s2, B);

    dim3 grid(NPTS / BN, NPTS / BM, B);  // (32, 32, 8)
    tile_min_kernel<<<grid, 256>>>(s1, s2);

    final_kernel<<<B, 256>>>(out);
}

// round 4
// speedup vs baseline: 4.4576x; 4.4576x over previous
#include <cuda_runtime.h>
#include <cuda_fp16.h>
#include <cstdint>
#include <math.h>

#define NPTS 4096
#define CDIM 128
#define BMAX 8
#define NT   32          // 4096 / 128 col tiles
#define TBYTES 32768     // one 128x128 fp16 tile in smem

// ------------------------- device scratch (no allocs) -------------------------
__device__ __half g_p1[(size_t)BMAX * NPTS * CDIM];
__device__ __half g_p2[(size_t)BMAX * NPTS * CDIM];
__device__ float g_sq1[BMAX * NPTS], g_sq2[BMAX * NPTS];
__device__ float g_rowmin[BMAX * NPTS];          // rs + min_col(cs - 2 inner)
__device__ unsigned g_colkey[BMAX * NPTS];       // flipped-uint of min_row(rs - 2 inner)

// ------------------------- helpers -------------------------
static __device__ __forceinline__ uint32_t smem_u32(const void* p) {
    uint32_t a;
    asm("{ .reg .u64 t; cvta.to.shared.u64 t, %1; cvt.u32.u64 %0, t; }" : "=r"(a) : "l"(p));
    return a;
}
static __device__ __forceinline__ void cp_async16(uint32_t sa, const void* ga) {
    asm volatile("cp.async.cg.shared.global [%0], [%1], 16;" :: "r"(sa), "l"(ga));
}
#define CP_COMMIT() asm volatile("cp.async.commit_group;" ::: "memory")
#define CP_WAIT_1() asm volatile("cp.async.wait_group 1;" ::: "memory")

static __device__ __forceinline__ void ldm_x4(uint32_t* r, uint32_t addr) {
    asm volatile("ldmatrix.sync.aligned.m8n8.x4.shared.b16 {%0,%1,%2,%3}, [%4];"
                 : "=r"(r[0]), "=r"(r[1]), "=r"(r[2]), "=r"(r[3]) : "r"(addr));
}
static __device__ __forceinline__ void mma16816(float* c, const uint32_t* a,
                                                const uint32_t* b) {
    asm volatile(
        "mma.sync.aligned.m16n8k16.row.col.f32.f16.f16.f32 "
        "{%0,%1,%2,%3}, {%4,%5,%6,%7}, {%8,%9}, {%0,%1,%2,%3};"
        : "+f"(c[0]), "+f"(c[1]), "+f"(c[2]), "+f"(c[3])
        : "r"(a[0]), "r"(a[1]), "r"(a[2]), "r"(a[3]), "r"(b[0]), "r"(b[1]));
}
// monotonic float->uint key (ascending floats -> ascending uints), any sign
static __device__ __forceinline__ unsigned fkey(float f) {
    unsigned u = __float_as_uint(f);
    return ((int)u < 0) ? ~u : (u | 0x80000000u);
}
static __device__ __forceinline__ float funkey(unsigned k) {
    unsigned u = (k & 0x80000000u) ? (k ^ 0x80000000u) : ~k;
    return __uint_as_float(u);
}

// SW128-swizzled tile: 2 k-blocks of 16KB; row r (0..127), k (0..127) fp16
// addr = base + (k>>6)*16384 + r*128 + (((k&63)*2) ^ ((r&7)*16))
static __device__ __forceinline__ void load_tile(uint32_t dst, const __half* src,
                                                 int tid) {
    const int r = tid & 127, s = tid >> 7;
    const char* gp = (const char*)(src + (size_t)r * CDIM + s * 64);
    const uint32_t base = dst + (uint32_t)s * 16384u + (uint32_t)r * 128u;
    const uint32_t x = (uint32_t)(r & 7) * 16u;
#pragma unroll
    for (int c = 0; c < 8; ++c)
        cp_async16(base + (((uint32_t)c * 16u) ^ x), gp + c * 16);
}

// smem layout (relative to 128-aligned base)
#define SM_A    0
#define SM_B    32768
#define SM_CS   98304
#define SM_CB   99328
#define SMEM_BYTES (99328 + 2048 + 128)

// ---------------------------------------------------------------------------
// Prep: fp32 -> fp16 + squared norms + colkey init. One warp per point.
// ---------------------------------------------------------------------------
__global__ void prep_kernel(const float* __restrict__ s1,
                            const float* __restrict__ s2, int B) {
    int gw = (blockIdx.x * blockDim.x + threadIdx.x) >> 5;
    int lane = threadIdx.x & 31;
    int total = B * NPTS;
    const float* src;
    __half2* dst;
    float* dsq;
    bool is2;
    int p;
    if (gw < total) {
        src = s1; p = gw; dst = (__half2*)g_p1; dsq = g_sq1; is2 = false;
    } else if (gw < 2 * total) {
        src = s2; p = gw - total; dst = (__half2*)g_p2; dsq = g_sq2; is2 = true;
    } else return;

    float4 f = ((const float4*)(src + (size_t)p * CDIM))[lane];
    dst[(size_t)p * 64 + lane * 2 + 0] = __floats2half2_rn(f.x, f.y);
    dst[(size_t)p * 64 + lane * 2 + 1] = __floats2half2_rn(f.z, f.w);

    float sq = f.x * f.x + f.y * f.y + f.z * f.z + f.w * f.w;
#pragma unroll
    for (int o = 16; o > 0; o >>= 1) sq += __shfl_xor_sync(0xffffffffu, sq, o);
    if (lane == 0) {
        dsq[p] = sq;
        if (is2) g_colkey[p] = 0xFFFFFFFFu;
    }
}

// ---------------------------------------------------------------------------
// Main: CTA = (row tile rt, batch b). A tile resident; stream 32 B tiles.
// mma.sync m16n8k16 fp16->fp32. Row mins in regs; col mins via shfl+smem+atomic.
// ---------------------------------------------------------------------------
__global__ __launch_bounds__(256, 2)
void hmma_main() {
    extern __shared__ char smraw[];
    const uint32_t raw = smem_u32(smraw);
    const uint32_t base = (raw + 127u) & ~127u;
    char* smp = smraw + (base - raw);

    const int tid = threadIdx.x, wid = tid >> 5, lane = tid & 31;
    const int wrow = wid >> 1, wcol = wid & 1;
    const int g = lane >> 2, tig = lane & 3;
    const int rt = blockIdx.x, b = blockIdx.y;

    const __half* A = g_p1 + ((size_t)(b * NPTS + rt * 128)) * CDIM;
    const __half* Bset = g_p2 + (size_t)b * NPTS * CDIM;
    const float* csq = g_sq2 + b * NPTS;
    const float* rsq = g_sq1 + b * NPTS + rt * 128;

    // prologue loads: group0 = A + B0 + cs0, group1 = B1 + cs1
    load_tile(base + SM_A, A, tid);
    load_tile(base + SM_B, Bset, tid);
    if (tid < 32) cp_async16(base + SM_CS + tid * 16u, csq + tid * 4);
    CP_COMMIT();
    load_tile(base + SM_B + TBYTES, Bset + 128 * CDIM, tid);
    if (tid < 32) cp_async16(base + SM_CS + 512u + tid * 16u, csq + 128 + tid * 4);
    CP_COMMIT();

    // this thread's 4 row slots: row = wrow*32 + i*16 + h*8 + g  (slot = i*2+h)
    float rsv[4], rowmin[4];
#pragma unroll
    for (int s = 0; s < 4; ++s) {
        rsv[s] = rsq[wrow * 32 + (s >> 1) * 16 + (s & 1) * 8 + g];
        rowmin[s] = INFINITY;
    }

    for (int ct = 0; ct < NT; ++ct) {
        CP_WAIT_1();
        __syncthreads();   // B(ct), cs(ct) resident

        const uint32_t bB = base + SM_B + (uint32_t)(ct & 1) * TBYTES;
        float acc[2][8][4];
#pragma unroll
        for (int i = 0; i < 2; ++i)
#pragma unroll
            for (int j = 0; j < 8; ++j)
#pragma unroll
                for (int c = 0; c < 4; ++c) acc[i][j][c] = 0.0f;

        const int blk = lane >> 3, l7 = lane & 7;
#pragma unroll
        for (int ks = 0; ks < 8; ++ks) {
            const int k0 = ks * 16;
            uint32_t af[2][4], bf[4][4];
#pragma unroll
            for (int i = 0; i < 2; ++i) {
                int row = wrow * 32 + i * 16 + (blk & 1) * 8 + l7;
                int kc = k0 + (blk >> 1) * 8;
                uint32_t ad = base + SM_A + (uint32_t)(kc >> 6) * 16384u +
                              (uint32_t)row * 128u +
                              ((((uint32_t)(kc & 63)) * 2u) ^ ((uint32_t)(row & 7) * 16u));
                ldm_x4(af[i], ad);
            }
#pragma unroll
            for (int j2 = 0; j2 < 4; ++j2) {
                int n = wcol * 64 + j2 * 16 + (blk >> 1) * 8 + l7;
                int kc = k0 + (blk & 1) * 8;
                uint32_t bd = bB + (uint32_t)(kc >> 6) * 16384u + (uint32_t)n * 128u +
                              ((((uint32_t)(kc & 63)) * 2u) ^ ((uint32_t)(n & 7) * 16u));
                ldm_x4(bf[j2], bd);
            }
#pragma unroll
            for (int i = 0; i < 2; ++i)
#pragma unroll
                for (int j = 0; j < 8; ++j)
                    mma16816(acc[i][j], af[i], &bf[j >> 1][(j & 1) * 2]);
        }

        // epilogue: cols for acc[i][j][c]: col = wcol*64 + j*8 + tig*2 + (c&1)
        //           rows:                  row slot = i*2 + (c>>1)
        const float* cs_f = (const float*)(smp + SM_CS + (ct & 1) * 512);
        float cmin[16];
#pragma unroll
        for (int t = 0; t < 16; ++t) cmin[t] = INFINITY;
#pragma unroll
        for (int j = 0; j < 8; ++j) {
            float c0 = cs_f[wcol * 64 + j * 8 + tig * 2 + 0];
            float c1 = cs_f[wcol * 64 + j * 8 + tig * 2 + 1];
#pragma unroll
            for (int i = 0; i < 2; ++i) {
                const float* a4 = acc[i][j];
                rowmin[i * 2 + 0] = fminf(rowmin[i * 2 + 0], fmaf(-2.0f, a4[0], c0));
                rowmin[i * 2 + 0] = fminf(rowmin[i * 2 + 0], fmaf(-2.0f, a4[1], c1));
                rowmin[i * 2 + 1] = fminf(rowmin[i * 2 + 1], fmaf(-2.0f, a4[2], c0));
                rowmin[i * 2 + 1] = fminf(rowmin[i * 2 + 1], fmaf(-2.0f, a4[3], c1));
                cmin[j * 2 + 0] = fminf(cmin[j * 2 + 0],
                    fminf(fmaf(-2.0f, a4[0], rsv[i * 2 + 0]),
                          fmaf(-2.0f, a4[2], rsv[i * 2 + 1])));
                cmin[j * 2 + 1] = fminf(cmin[j * 2 + 1],
                    fminf(fmaf(-2.0f, a4[1], rsv[i * 2 + 0]),
                          fmaf(-2.0f, a4[3], rsv[i * 2 + 1])));
            }
        }
        // reduce col mins across the 8 row-groups (g) in the warp
#pragma unroll
        for (int t = 0; t < 16; ++t) {
#pragma unroll
            for (int d = 4; d < 32; d <<= 1)
                cmin[t] = fminf(cmin[t], __shfl_xor_sync(0xffffffffu, cmin[t], d));
        }

        __syncthreads();   // all smem reads of B(ct)/cs(ct)/colbuf(prev) done
        if (ct + 2 < NT) {
            load_tile(base + SM_B + (uint32_t)(ct & 1) * TBYTES,
                      Bset + (size_t)(ct + 2) * 128 * CDIM, tid);
            if (tid < 32)
                cp_async16(base + SM_CS + (uint32_t)(ct & 1) * 512u + tid * 16u,
                           csq + (ct + 2) * 128 + tid * 4);
        }
        CP_COMMIT();       // always commit to keep group accounting aligned

        float* cb = (float*)(smp + SM_CB);
        if (g == 0) {
#pragma unroll
            for (int j = 0; j < 8; ++j) {
                cb[wrow * 128 + wcol * 64 + j * 8 + tig * 2 + 0] = cmin[j * 2 + 0];
                cb[wrow * 128 + wcol * 64 + j * 8 + tig * 2 + 1] = cmin[j * 2 + 1];
            }
        }
        __syncthreads();
        if (tid < 128) {
            float v = fminf(fminf(cb[tid], cb[128 + tid]),
                            fminf(cb[256 + tid], cb[384 + tid]));
            atomicMin(&g_colkey[b * NPTS + ct * 128 + tid], fkey(v));
        }
    }

    // final row-min: reduce across tig lanes, then the 2 warp-cols
#pragma unroll
    for (int s = 0; s < 4; ++s) {
#pragma unroll
        for (int d = 1; d < 4; d <<= 1)
            rowmin[s] = fminf(rowmin[s], __shfl_xor_sync(0xffffffffu, rowmin[s], d));
    }
    __syncthreads();
    float* rb = (float*)(smp + SM_CB);
    if (tig == 0) {
#pragma unroll
        for (int s = 0; s < 4; ++s)
            rb[wcol * 128 + wrow * 32 + (s >> 1) * 16 + (s & 1) * 8 + g] = rowmin[s];
    }
    __syncthreads();
    if (tid < 128) {
        float m = fminf(rb[tid], rb[128 + tid]);
        g_rowmin[b * NPTS + rt * 128 + tid] = rsq[tid] + m;
    }
}

// ---------------------------------------------------------------------------
// Finalize: mean over rows of sqrt(max(rowmin,0)) + mean over cols of
// sqrt(max(cs + decode(colkey), 0)).
// ---------------------------------------------------------------------------
__global__ void final_kernel(float* __restrict__ out) {
    const int b = blockIdx.x;
    const int tid = threadIdx.x;
    float s = 0.0f;
    for (int i = tid; i < NPTS; i += blockDim.x) {
        s += sqrtf(fmaxf(g_rowmin[b * NPTS + i], 0.0f));
        float cv = funkey(g_colkey[b * NPTS + i]);
        s += sqrtf(fmaxf(g_sq2[b * NPTS + i] + cv, 0.0f));
    }
    __shared__ float red[256];
    red[tid] = s;
    __syncthreads();
    for (int st = 128; st > 0; st >>= 1) {
        if (tid < st) red[tid] += red[tid + st];
        __syncthreads();
    }
    if (tid == 0) out[b] = red[0] / (float)NPTS;
}

// ---------------------------------------------------------------------------
extern "C" void kernel_launch(void* const* d_in, const int* in_sizes, int n_in,
                              void* d_out, int out_size) {
    const float* s1 = (const float*)d_in[0];
    const float* s2 = (const float*)d_in[1];
    float* out = (float*)d_out;
    const int B = in_sizes[0] / (NPTS * CDIM);   // 8

    static bool attr_set = false;
    if (!attr_set) {
        cudaFuncSetAttribute(hmma_main,
                             cudaFuncAttributeMaxDynamicSharedMemorySize, SMEM_BYTES);
        attr_set = true;
    }

    int threads = 2 * B * NPTS * 32;
    prep_kernel<<<(threads + 255) / 256, 256>>>(s1, s2, B);

    dim3 grid(NT, B);
    hmma_main<<<grid, 256, SMEM_BYTES>>>();

    final_kernel<<<B, 256>>>(out);
}

// round 8
// speedup vs baseline: 4.5804x; 1.0275x over previous
#include <cuda_runtime.h>
#include <cuda_fp16.h>
#include <cstdint>
#include <math.h>

#define NPTS 4096
#define CDIM 128
#define BMAX 8
#define NTH  16          // col tiles per CTA (half of 32)
#define COLS_PER_CTA 2048
#define TBYTES 32768     // one 128x128 fp16 tile in smem

// ------------------------- device scratch (no allocs) -------------------------
__device__ __half g_p1[(size_t)BMAX * NPTS * CDIM];
__device__ __half g_p2[(size_t)BMAX * NPTS * CDIM];
__device__ float g_sq1[BMAX * NPTS], g_sq2[BMAX * NPTS];
__device__ unsigned g_rowkey[BMAX * NPTS];   // flipped-uint of min_col(cs - 2 inner)
__device__ unsigned g_colkey[BMAX * NPTS];   // flipped-uint of min_row(rs - 2 inner)

// ------------------------- helpers -------------------------
static __device__ __forceinline__ uint32_t smem_u32(const void* p) {
    uint32_t a;
    asm("{ .reg .u64 t; cvta.to.shared.u64 t, %1; cvt.u32.u64 %0, t; }" : "=r"(a) : "l"(p));
    return a;
}
static __device__ __forceinline__ void cp_async16(uint32_t sa, const void* ga) {
    asm volatile("cp.async.cg.shared.global [%0], [%1], 16;" :: "r"(sa), "l"(ga));
}
#define CP_COMMIT() asm volatile("cp.async.commit_group;" ::: "memory")
#define CP_WAIT_1() asm volatile("cp.async.wait_group 1;" ::: "memory")

static __device__ __forceinline__ void ldm_x4(uint32_t* r, uint32_t addr) {
    asm volatile("ldmatrix.sync.aligned.m8n8.x4.shared.b16 {%0,%1,%2,%3}, [%4];"
                 : "=r"(r[0]), "=r"(r[1]), "=r"(r[2]), "=r"(r[3]) : "r"(addr));
}
static __device__ __forceinline__ void mma16816(float* c, const uint32_t* a,
                                                const uint32_t* b) {
    asm volatile(
        "mma.sync.aligned.m16n8k16.row.col.f32.f16.f16.f32 "
        "{%0,%1,%2,%3}, {%4,%5,%6,%7}, {%8,%9}, {%0,%1,%2,%3};"
        : "+f"(c[0]), "+f"(c[1]), "+f"(c[2]), "+f"(c[3])
        : "r"(a[0]), "r"(a[1]), "r"(a[2]), "r"(a[3]), "r"(b[0]), "r"(b[1]));
}
// monotonic float<->uint order-preserving key (handles negatives)
static __device__ __forceinline__ unsigned fkey(float f) {
    unsigned u = __float_as_uint(f);
    return ((int)u < 0) ? ~u : (u | 0x80000000u);
}
static __device__ __forceinline__ float funkey(unsigned k) {
    unsigned u = (k & 0x80000000u) ? (k ^ 0x80000000u) : ~k;
    return __uint_as_float(u);
}

// SW128-swizzled tile: 2 k-blocks of 16KB; row r (0..127), k (0..127) fp16
static __device__ __forceinline__ void load_tile(uint32_t dst, const __half* src,
                                                 int tid) {
    const int r = tid & 127, s = tid >> 7;
    const char* gp = (const char*)(src + (size_t)r * CDIM + s * 64);
    const uint32_t base = dst + (uint32_t)s * 16384u + (uint32_t)r * 128u;
    const uint32_t x = (uint32_t)(r & 7) * 16u;
#pragma unroll
    for (int c = 0; c < 8; ++c)
        cp_async16(base + (((uint32_t)c * 16u) ^ x), gp + c * 16);
}
static __device__ __forceinline__ uint32_t sw_addr(uint32_t tb, int row, int kc) {
    return tb + (uint32_t)(kc >> 6) * 16384u + (uint32_t)row * 128u +
           ((((uint32_t)(kc & 63)) * 2u) ^ ((uint32_t)(row & 7) * 16u));
}

// smem layout (relative to 128-aligned base)
#define SM_A    0
#define SM_B    32768
#define SM_CS   98304
#define SMEM_BYTES (98304 + 1024 + 128)

// ---------------------------------------------------------------------------
// Prep: fp32 -> fp16 + squared norms + key init. One warp per point.
// ---------------------------------------------------------------------------
__global__ void prep_kernel(const float* __restrict__ s1,
                            const float* __restrict__ s2, int B) {
    int gw = (blockIdx.x * blockDim.x + threadIdx.x) >> 5;
    int lane = threadIdx.x & 31;
    int total = B * NPTS;
    const float* src;
    __half2* dst;
    float* dsq;
    unsigned* key;
    int p;
    if (gw < total) {
        src = s1; p = gw; dst = (__half2*)g_p1; dsq = g_sq1; key = g_rowkey;
    } else if (gw < 2 * total) {
        src = s2; p = gw - total; dst = (__half2*)g_p2; dsq = g_sq2; key = g_colkey;
    } else return;

    float4 f = ((const float4*)(src + (size_t)p * CDIM))[lane];
    dst[(size_t)p * 64 + lane * 2 + 0] = __floats2half2_rn(f.x, f.y);
    dst[(size_t)p * 64 + lane * 2 + 1] = __floats2half2_rn(f.z, f.w);

    float sq = f.x * f.x + f.y * f.y + f.z * f.z + f.w * f.w;
#pragma unroll
    for (int o = 16; o > 0; o >>= 1) sq += __shfl_xor_sync(0xffffffffu, sq, o);
    if (lane == 0) { dsq[p] = sq; key[p] = 0xFFFFFFFFu; }
}

// ---------------------------------------------------------------------------
// Main: CTA = (row tile rt, batch b, col half ch). A tile resident; streams
// 16 B tiles of its half. Warp tile 64x32 (wrow in {0,1}, wcol in {0..3}).
// Row mins in regs -> global atomicMin at end; col mins reduce-scattered via
// shfl -> one predicated red.global.min.u32 per warp per tile.
// ---------------------------------------------------------------------------
__global__ __launch_bounds__(256, 2)
void hmma_main() {
    extern __shared__ char smraw[];
    const uint32_t raw = smem_u32(smraw);
    const uint32_t base = (raw + 127u) & ~127u;
    char* smp = smraw + (base - raw);

    const int tid = threadIdx.x, wid = tid >> 5, lane = tid & 31;
    const int wrow = wid & 1, wcol = wid >> 1;      // 2 x 4 warp grid
    const int g = lane >> 2, tig = lane & 3;
    const int rt = blockIdx.x, b = blockIdx.y, ch = blockIdx.z;

    const __half* A = g_p1 + ((size_t)(b * NPTS + rt * 128)) * CDIM;
    const __half* Bset = g_p2 + ((size_t)(b * NPTS + ch * COLS_PER_CTA)) * CDIM;
    const float* csq = g_sq2 + b * NPTS + ch * COLS_PER_CTA;
    const float* rsq = g_sq1 + b * NPTS + rt * 128;

    // prologue: group0 = A + B0 + cs0, group1 = B1 + cs1
    load_tile(base + SM_A, A, tid);
    load_tile(base + SM_B, Bset, tid);
    if (tid < 32) cp_async16(base + SM_CS + tid * 16u, csq + tid * 4);
    CP_COMMIT();
    load_tile(base + SM_B + TBYTES, Bset + 128 * CDIM, tid);
    if (tid < 32) cp_async16(base + SM_CS + 512u + tid * 16u, csq + 128 + tid * 4);
    CP_COMMIT();

    // row slot s (0..7): row = wrow*64 + (s>>1)*16 + (s&1)*8 + g
    float rsv[8], rowmin[8];
#pragma unroll
    for (int s = 0; s < 8; ++s) {
        rsv[s] = rsq[wrow * 64 + (s >> 1) * 16 + (s & 1) * 8 + g];
        rowmin[s] = INFINITY;
    }

    const int blk = lane >> 3, l7 = lane & 7;

    for (int ct = 0; ct < NTH; ++ct) {
        CP_WAIT_1();
        __syncthreads();   // B(ct), cs(ct) resident

        const uint32_t bA = base + SM_A;
        const uint32_t bB = base + SM_B + (uint32_t)(ct & 1) * TBYTES;
        float acc[4][4][4];
#pragma unroll
        for (int i = 0; i < 4; ++i)
#pragma unroll
            for (int j = 0; j < 4; ++j)
#pragma unroll
                for (int c = 0; c < 4; ++c) acc[i][j][c] = 0.0f;

#pragma unroll
        for (int ks = 0; ks < 8; ++ks) {
            const int k0 = ks * 16;
            uint32_t af[4][4], bf[2][4];
#pragma unroll
            for (int i = 0; i < 4; ++i)
                ldm_x4(af[i], sw_addr(bA, wrow * 64 + i * 16 + (blk & 1) * 8 + l7,
                                      k0 + (blk >> 1) * 8));
#pragma unroll
            for (int j2 = 0; j2 < 2; ++j2)
                ldm_x4(bf[j2], sw_addr(bB, wcol * 32 + j2 * 16 + (blk >> 1) * 8 + l7,
                                       k0 + (blk & 1) * 8));
#pragma unroll
            for (int i = 0; i < 4; ++i)
#pragma unroll
                for (int j = 0; j < 4; ++j)
                    mma16816(acc[i][j], af[i], &bf[j >> 1][(j & 1) * 2]);
        }

        // epilogue. acc[i][j][c]: row = wrow*64+i*16+(c>>1)*8+g (slot i*2+(c>>1))
        //                         col = wcol*32+j*8+tig*2+(c&1)  (cmin t=j*2+(c&1))
        const float* cs_f = (const float*)(smp + SM_CS + (ct & 1) * 512);
        float cmin[8];
#pragma unroll
        for (int t = 0; t < 8; ++t) cmin[t] = INFINITY;
#pragma unroll
        for (int j = 0; j < 4; ++j) {
            float c0 = cs_f[wcol * 32 + j * 8 + tig * 2 + 0];
            float c1 = cs_f[wcol * 32 + j * 8 + tig * 2 + 1];
#pragma unroll
            for (int i = 0; i < 4; ++i) {
                const float* a4 = acc[i][j];
                rowmin[i * 2 + 0] = fminf(rowmin[i * 2 + 0],
                    fminf(fmaf(-2.0f, a4[0], c0), fmaf(-2.0f, a4[1], c1)));
                rowmin[i * 2 + 1] = fminf(rowmin[i * 2 + 1],
                    fminf(fmaf(-2.0f, a4[2], c0), fmaf(-2.0f, a4[3], c1)));
                cmin[j * 2 + 0] = fminf(cmin[j * 2 + 0],
                    fminf(fmaf(-2.0f, a4[0], rsv[i * 2 + 0]),
                          fmaf(-2.0f, a4[2], rsv[i * 2 + 1])));
                cmin[j * 2 + 1] = fminf(cmin[j * 2 + 1],
                    fminf(fmaf(-2.0f, a4[1], rsv[i * 2 + 0]),
                          fmaf(-2.0f, a4[3], rsv[i * 2 + 1])));
            }
        }
        // reduce-scatter cmin over g (lane = g*4 + tig): 7 shfls.
#pragma unroll
        for (int t = 0; t < 4; ++t) {
            float keep = (g & 1) ? cmin[t + 4] : cmin[t];
            float send = (g & 1) ? cmin[t] : cmin[t + 4];
            cmin[t] = fminf(keep, __shfl_xor_sync(0xffffffffu, send, 4));
        }
#pragma unroll
        for (int t = 0; t < 2; ++t) {
            float keep = (g & 2) ? cmin[t + 2] : cmin[t];
            float send = (g & 2) ? cmin[t] : cmin[t + 2];
            cmin[t] = fminf(keep, __shfl_xor_sync(0xffffffffu, send, 8));
        }
        {
            float keep = (g & 4) ? cmin[1] : cmin[0];
            float send = (g & 4) ? cmin[0] : cmin[1];
            cmin[0] = fminf(keep, __shfl_xor_sync(0xffffffffu, send, 16));
        }
        // lane owns logical t = bit-reversed g
        const int t = ((g & 1) << 2) | (g & 2) | ((g >> 2) & 1);
        const int col = wcol * 32 + ((t >> 1) << 3) + tig * 2 + (t & 1);
        atomicMin(&g_colkey[b * NPTS + ch * COLS_PER_CTA + ct * 128 + col],
                  fkey(cmin[0]));

        __syncthreads();   // all smem reads of B(ct)/cs(ct) done
        if (ct + 2 < NTH) {
            load_tile(base + SM_B + (uint32_t)(ct & 1) * TBYTES,
                      Bset + (size_t)(ct + 2) * 128 * CDIM, tid);
            if (tid < 32)
                cp_async16(base + SM_CS + (uint32_t)(ct & 1) * 512u + tid * 16u,
                           csq + (ct + 2) * 128 + tid * 4);
        }
        CP_COMMIT();
    }

    // row mins: full reduce over tig, then tig==0 lanes write 8 rows each.
#pragma unroll
    for (int s = 0; s < 8; ++s) {
        rowmin[s] = fminf(rowmin[s], __shfl_xor_sync(0xffffffffu, rowmin[s], 1));
        rowmin[s] = fminf(rowmin[s], __shfl_xor_sync(0xffffffffu, rowmin[s], 2));
    }
    if (tig == 0) {
#pragma unroll
        for (int s = 0; s < 8; ++s) {
            int row = wrow * 64 + (s >> 1) * 16 + (s & 1) * 8 + g;
            atomicMin(&g_rowkey[b * NPTS + rt * 128 + row], fkey(rowmin[s]));
        }
    }
}

// ---------------------------------------------------------------------------
// Finalize: mean of sqrt(max(norm + decode(key), 0)) over both directions.
// ---------------------------------------------------------------------------
__global__ void final_kernel(float* __restrict__ out) {
    const int b = blockIdx.x;
    const int tid = threadIdx.x;
    float s = 0.0f;
    for (int i = tid; i < NPTS; i += blockDim.x) {
        s += sqrtf(fmaxf(g_sq1[b * NPTS + i] + funkey(g_rowkey[b * NPTS + i]), 0.0f));
        s += sqrtf(fmaxf(g_sq2[b * NPTS + i] + funkey(g_colkey[b * NPTS + i]), 0.0f));
    }
    __shared__ float red[256];
    red[tid] = s;
    __syncthreads();
    for (int st = 128; st > 0; st >>= 1) {
        if (tid < st) red[tid] += red[tid + st];
        __syncthreads();
    }
    if (tid == 0) out[b] = red[0] / (float)NPTS;
}

// ---------------------------------------------------------------------------
extern "C" void kernel_launch(void* const* d_in, const int* in_sizes, int n_in,
                              void* d_out, int out_size) {
    const float* s1 = (const float*)d_in[0];
    const float* s2 = (const float*)d_in[1];
    float* out = (float*)d_out;
    const int B = in_sizes[0] / (NPTS * CDIM);   // 8

    static bool attr_set = false;
    if (!attr_set) {
        cudaFuncSetAttribute(hmma_main,
                             cudaFuncAttributeMaxDynamicSharedMemorySize, SMEM_BYTES);
        attr_set = true;
    }

    int threads = 2 * B * NPTS * 32;
    prep_kernel<<<(threads + 255) / 256, 256>>>(s1, s2, B);

    dim3 grid(NPTS / 128, B, 2);   // (32, 8, 2) = 512 CTAs
    hmma_main<<<grid, 256, SMEM_BYTES>>>();

    final_kernel<<<B, 256>>>(out);
}